// round 16
// baseline (speedup 1.0000x reference)
#include <cuda_runtime.h>
#include <cuda.h>
#include <cuda_bf16.h>
#include <cstdint>

#define D_MODEL 4096
#define NB 8
#define ROW_F4 (D_MODEL / 4)     // 1024 float4 per row
#define TMA_THREADS 256          // each thread -> 4 consecutive float4 (16 floats)
#define ROW_BYTES (D_MODEL * 4)  // 16 KB
#define HALF_CHUNKS 64           // 64 of 128 dim1-chunks = half a row

// ---------------- swizzled smem access (SW128: bits[6:4] ^= bits[9:7]) -----
__device__ __forceinline__ unsigned swz(unsigned byte_off) {
    return byte_off ^ ((byte_off >> 3) & 0x70u);
}
__device__ __forceinline__ float4 lds_win(const float* s, int j) {
    if ((unsigned)j >= (unsigned)ROW_F4)      // outside row -> band clipped
        return make_float4(0.f, 0.f, 0.f, 0.f);
    unsigned off = swz(((unsigned)j) << 4);
    return *reinterpret_cast<const float4*>(reinterpret_cast<const char*>(s) + off);
}
__device__ __forceinline__ void sts_swz(float* s, int j, float4 v) {
    unsigned off = swz(((unsigned)j) << 4);
    *reinterpret_cast<float4*>(reinterpret_cast<char*>(s) + off) = v;
}
__device__ __forceinline__ void mbar_wait(unsigned mb, unsigned parity) {
    unsigned done = 0;
    do {
        asm volatile(
            "{\n\t.reg .pred p;\n\t"
            "mbarrier.try_wait.parity.acquire.cta.shared::cta.b64 p, [%1], %2, 0x989680;\n\t"
            "selp.b32 %0, 1, 0, p;\n\t}"
            : "=r"(done) : "r"(mb), "r"(parity) : "memory");
    } while (!done);
}

// ------- TMA kernel: one block = one row, split (overlapped) store ---------
__global__ __launch_bounds__(TMA_THREADS)
void li_tma_kernel(const __grid_constant__ CUtensorMap tmin,
                   const __grid_constant__ CUtensorMap tmout,
                   const float* __restrict__ Kmat) {
    __shared__ alignas(1024) float s_in[D_MODEL];
    __shared__ alignas(1024) float s_out[D_MODEL];
    __shared__ alignas(8) unsigned long long mbar;

    const int t   = threadIdx.x;
    const int row = blockIdx.x;

    const unsigned smem_in  = (unsigned)__cvta_generic_to_shared(s_in);
    const unsigned smem_out = (unsigned)__cvta_generic_to_shared(s_out);
    const unsigned mb       = (unsigned)__cvta_generic_to_shared(&mbar);

    if (t == 0) {
        asm volatile("mbarrier.init.shared.b64 [%0], %1;" :: "r"(mb), "r"(1) : "memory");
        asm volatile("mbarrier.arrive.expect_tx.shared.b64 _, [%0], %1;"
                     :: "r"(mb), "r"((unsigned)ROW_BYTES) : "memory");
        asm volatile(
            "cp.async.bulk.tensor.3d.shared::cta.global.tile.mbarrier::complete_tx::bytes "
            "[%0], [%1, {%2, %3, %4}], [%5];"
            :: "r"(smem_in), "l"(&tmin), "r"(0), "r"(0), "r"(row), "r"(mb) : "memory");
    }

    // Band weights while TMA is in flight: K[0][d] = -strength/(1+d), d = 1..8
    float w[NB + 1];
#pragma unroll
    for (int d = 1; d <= NB; d++) w[d] = __ldg(Kmat + d);

    __syncthreads();
    mbar_wait(mb, 0);

    // Sliding 5-float4 window over this thread's 4 consecutive output f4s.
    // 64B lane stride is conflict-free under SW128 (verified per 8-lane phase).
    const int j0 = 4 * t;
    float4 win[5];
#pragma unroll
    for (int m = 0; m < 4; m++) win[m] = lds_win(s_in, j0 - 2 + m);

#pragma unroll
    for (int k = 0; k < 4; k++) {
        win[4] = lds_win(s_in, j0 + 2 + k);

        float f[20];
#pragma unroll
        for (int m = 0; m < 5; m++) {
            f[4*m+0] = win[m].x; f[4*m+1] = win[m].y;
            f[4*m+2] = win[m].z; f[4*m+3] = win[m].w;
        }
        float o[4];
#pragma unroll
        for (int q = 0; q < 4; q++) {
            const int c = NB + q;
            float acc = f[c];                 // identity term A[i]
#pragma unroll
            for (int d = 1; d <= NB; d++)
                acc = fmaf(w[d], f[c - d] + f[c + d], acc);
            o[q] = acc;
        }
        sts_swz(s_out, j0 + k, make_float4(o[0], o[1], o[2], o[3]));

        win[0] = win[1]; win[1] = win[2]; win[2] = win[3]; win[3] = win[4];
    }

    // --- first half (warps 0-3 own j0 < 512): store while warps 4-7 compute
    if (t < 128) {
        asm volatile("bar.sync 1, 128;" ::: "memory");
        if (t == 0) {
            asm volatile("fence.proxy.async.shared::cta;" ::: "memory");
            asm volatile(
                "cp.async.bulk.tensor.3d.global.shared::cta.tile.bulk_group "
                "[%0, {%1, %2, %3}], [%4];"
                :: "l"(&tmout), "r"(0), "r"(0), "r"(row), "r"(smem_out) : "memory");
            asm volatile("cp.async.bulk.commit_group;" ::: "memory");
        }
    }

    // --- second half after everyone is done
    __syncthreads();
    asm volatile("fence.proxy.async.shared::cta;" ::: "memory");
    if (t == 0) {
        asm volatile(
            "cp.async.bulk.tensor.3d.global.shared::cta.tile.bulk_group "
            "[%0, {%1, %2, %3}], [%4];"
            :: "l"(&tmout), "r"(0), "r"(HALF_CHUNKS), "r"(row),
               "r"(smem_out + HALF_CHUNKS * 128) : "memory");
        asm volatile("cp.async.bulk.commit_group;" ::: "memory");
        asm volatile("cp.async.bulk.wait_group 0;" ::: "memory");
    }
}

// ---------------- fallback (round-4 kernel, proven 92.9us) -----------------
#define FB_THREADS 256
#define FB_CHUNKS 2
__global__ __launch_bounds__(FB_THREADS)
void li_fallback_kernel(const float* __restrict__ A,
                        const float* __restrict__ Kmat,
                        float* __restrict__ Out) {
    const int row = blockIdx.y;
    const int t   = threadIdx.x;
    const int p0  = blockIdx.x * (FB_THREADS * FB_CHUNKS) + t;
    const float4* __restrict__ arow4 =
        reinterpret_cast<const float4*>(A + (size_t)row * D_MODEL);
    float4* __restrict__ orow4 =
        reinterpret_cast<float4*>(Out + (size_t)row * D_MODEL);
    float w[NB + 1];
#pragma unroll
    for (int d = 1; d <= NB; d++) w[d] = __ldg(Kmat + d);
    float f[FB_CHUNKS][20];
#pragma unroll
    for (int c = 0; c < FB_CHUNKS; c++) {
        const int p = p0 + c * FB_THREADS;
        if (p >= 2 && p < ROW_F4 - 2) {
            const float4* __restrict__ base = arow4 + p;
#pragma unroll
            for (int m = 0; m < 5; m++) {
                float4 q = base[m - 2];
                f[c][4*m+0] = q.x; f[c][4*m+1] = q.y;
                f[c][4*m+2] = q.z; f[c][4*m+3] = q.w;
            }
        } else {
#pragma unroll
            for (int m = 0; m < 5; m++) {
                const int idx = p + m - 2;
                float4 q = make_float4(0.f, 0.f, 0.f, 0.f);
                if (idx >= 0 && idx < ROW_F4) q = arow4[idx];
                f[c][4*m+0] = q.x; f[c][4*m+1] = q.y;
                f[c][4*m+2] = q.z; f[c][4*m+3] = q.w;
            }
        }
    }
#pragma unroll
    for (int c = 0; c < FB_CHUNKS; c++) {
        float o[4];
#pragma unroll
        for (int k = 0; k < 4; k++) {
            const int ctr = NB + k;
            float acc = f[c][ctr];
#pragma unroll
            for (int d = 1; d <= NB; d++)
                acc = fmaf(w[d], f[c][ctr - d] + f[c][ctr + d], acc);
            o[k] = acc;
        }
        __stcs(orow4 + p0 + c * FB_THREADS, make_float4(o[0], o[1], o[2], o[3]));
    }
}

// ---------------- host: tensormap encode via driver entry point ------------
typedef CUresult (*PFN_encode)(
    CUtensorMap*, CUtensorMapDataType, cuuint32_t, void*,
    const cuuint64_t*, const cuuint64_t*, const cuuint32_t*, const cuuint32_t*,
    CUtensorMapInterleave, CUtensorMapSwizzle, CUtensorMapL2promotion,
    CUtensorMapFloatOOBfill);

static PFN_encode get_encode() {
    static PFN_encode fn = nullptr;
    static bool tried = false;
    if (!tried) {
        tried = true;
        void* p = nullptr;
        cudaDriverEntryPointQueryResult st;
#if CUDART_VERSION >= 12050
        if (cudaGetDriverEntryPointByVersion("cuTensorMapEncodeTiled", &p, 12000,
                                             cudaEnableDefault, &st) == cudaSuccess &&
            st == cudaDriverEntryPointSuccess && p)
            fn = (PFN_encode)p;
#else
        if (cudaGetDriverEntryPoint("cuTensorMapEncodeTiled", &p,
                                    cudaEnableDefault, &st) == cudaSuccess && p)
            fn = (PFN_encode)p;
#endif
    }
    return fn;
}

static bool make_map(PFN_encode enc, CUtensorMap* tm, void* base, int rows,
                     unsigned box_chunks) {
    // View (rows, 4096) fp32 as 3D: dim0=32 floats (128B SW128 atom),
    // dim1=128 chunks, dim2=rows. Box covers box_chunks dim1-chunks.
    cuuint64_t dims[3]    = {32, 128, (cuuint64_t)rows};
    cuuint64_t strides[2] = {128, (cuuint64_t)D_MODEL * 4};  // bytes
    cuuint32_t box[3]     = {32, box_chunks, 1};
    cuuint32_t es[3]      = {1, 1, 1};
    return enc(tm, CU_TENSOR_MAP_DATA_TYPE_FLOAT32, 3, base, dims, strides, box, es,
               CU_TENSOR_MAP_INTERLEAVE_NONE, CU_TENSOR_MAP_SWIZZLE_128B,
               CU_TENSOR_MAP_L2_PROMOTION_L2_128B,
               CU_TENSOR_MAP_FLOAT_OOB_FILL_NONE) == CUDA_SUCCESS;
}

extern "C" void kernel_launch(void* const* d_in, const int* in_sizes, int n_in,
                              void* d_out, int out_size) {
    const float* A    = (const float*)d_in[0];   // activations (rows, 4096)
    const float* Kmat = (const float*)d_in[1];   // inhibition kernel (4096, 4096)
    float* Out        = (float*)d_out;
    const int rows    = in_sizes[0] / D_MODEL;   // 16384

    PFN_encode enc = get_encode();
    if (enc) {
        CUtensorMap tmin, tmout;
        if (make_map(enc, &tmin, (void*)A, rows, 128) &&          // full-row load
            make_map(enc, &tmout, (void*)Out, rows, HALF_CHUNKS)) { // half-row store
            li_tma_kernel<<<rows, TMA_THREADS>>>(tmin, tmout, Kmat);
            return;
        }
    }
    // Fallback: proven direct-LDG kernel
    dim3 grid(ROW_F4 / (FB_THREADS * FB_CHUNKS), rows);
    li_fallback_kernel<<<grid, FB_THREADS>>>(A, Kmat, Out);
}

// round 17
// speedup vs baseline: 1.0095x; 1.0095x over previous
#include <cuda_runtime.h>
#include <cuda.h>
#include <cuda_bf16.h>
#include <cstdint>

#define D_MODEL 4096
#define NB 8
#define ROW_F4 (D_MODEL / 4)     // 1024 float4 per row
#define TMA_THREADS 256          // each thread -> 4 consecutive float4 (16 floats)
#define ROW_BYTES (D_MODEL * 4)  // 16 KB

// ---------------- swizzled smem access (SW128: bits[6:4] ^= bits[9:7]) -----
__device__ __forceinline__ unsigned swz(unsigned byte_off) {
    return byte_off ^ ((byte_off >> 3) & 0x70u);
}
__device__ __forceinline__ float4 lds_win(const float* s, int j) {
    if ((unsigned)j >= (unsigned)ROW_F4)      // outside row -> band clipped
        return make_float4(0.f, 0.f, 0.f, 0.f);
    unsigned off = swz(((unsigned)j) << 4);
    return *reinterpret_cast<const float4*>(reinterpret_cast<const char*>(s) + off);
}
__device__ __forceinline__ void sts_swz(float* s, int j, float4 v) {
    unsigned off = swz(((unsigned)j) << 4);
    *reinterpret_cast<float4*>(reinterpret_cast<char*>(s) + off) = v;
}
__device__ __forceinline__ void mbar_wait(unsigned mb, unsigned parity) {
    unsigned done = 0;
    do {
        asm volatile(
            "{\n\t.reg .pred p;\n\t"
            "mbarrier.try_wait.parity.acquire.cta.shared::cta.b64 p, [%1], %2, 0x989680;\n\t"
            "selp.b32 %0, 1, 0, p;\n\t}"
            : "=r"(done) : "r"(mb), "r"(parity) : "memory");
    } while (!done);
}

// ---------------- TMA kernel: one block = one row (best measured) ----------
__global__ __launch_bounds__(TMA_THREADS)
void li_tma_kernel(const __grid_constant__ CUtensorMap tmin,
                   const __grid_constant__ CUtensorMap tmout,
                   const float* __restrict__ Kmat) {
    __shared__ alignas(1024) float s_in[D_MODEL];
    __shared__ alignas(1024) float s_out[D_MODEL];
    __shared__ alignas(8) unsigned long long mbar;

    const int t   = threadIdx.x;
    const int row = blockIdx.x;

    const unsigned smem_in  = (unsigned)__cvta_generic_to_shared(s_in);
    const unsigned smem_out = (unsigned)__cvta_generic_to_shared(s_out);
    const unsigned mb       = (unsigned)__cvta_generic_to_shared(&mbar);

    if (t == 0) {
        asm volatile("mbarrier.init.shared.b64 [%0], %1;" :: "r"(mb), "r"(1) : "memory");
        asm volatile("mbarrier.arrive.expect_tx.shared.b64 _, [%0], %1;"
                     :: "r"(mb), "r"((unsigned)ROW_BYTES) : "memory");
        asm volatile(
            "cp.async.bulk.tensor.3d.shared::cta.global.tile.mbarrier::complete_tx::bytes "
            "[%0], [%1, {%2, %3, %4}], [%5];"
            :: "r"(smem_in), "l"(&tmin), "r"(0), "r"(0), "r"(row), "r"(mb) : "memory");
    }

    // Band weights while TMA is in flight: K[0][d] = -strength/(1+d), d = 1..8
    float w[NB + 1];
#pragma unroll
    for (int d = 1; d <= NB; d++) w[d] = __ldg(Kmat + d);

    __syncthreads();
    mbar_wait(mb, 0);

    // Sliding 5-float4 window over this thread's 4 consecutive output f4s.
    // 64B lane stride is conflict-free under SW128 (verified per 8-lane phase).
    const int j0 = 4 * t;
    float4 win[5];
#pragma unroll
    for (int m = 0; m < 4; m++) win[m] = lds_win(s_in, j0 - 2 + m);

#pragma unroll
    for (int k = 0; k < 4; k++) {
        win[4] = lds_win(s_in, j0 + 2 + k);

        float f[20];
#pragma unroll
        for (int m = 0; m < 5; m++) {
            f[4*m+0] = win[m].x; f[4*m+1] = win[m].y;
            f[4*m+2] = win[m].z; f[4*m+3] = win[m].w;
        }
        float o[4];
#pragma unroll
        for (int q = 0; q < 4; q++) {
            const int c = NB + q;
            float acc = f[c];                 // identity term A[i]
#pragma unroll
            for (int d = 1; d <= NB; d++)
                acc = fmaf(w[d], f[c - d] + f[c + d], acc);
            o[q] = acc;
        }
        sts_swz(s_out, j0 + k, make_float4(o[0], o[1], o[2], o[3]));

        win[0] = win[1]; win[1] = win[2]; win[2] = win[3]; win[3] = win[4];
    }

    __syncthreads();
    asm volatile("fence.proxy.async.shared::cta;" ::: "memory");
    if (t == 0) {
        asm volatile(
            "cp.async.bulk.tensor.3d.global.shared::cta.tile.bulk_group "
            "[%0, {%1, %2, %3}], [%4];"
            :: "l"(&tmout), "r"(0), "r"(0), "r"(row), "r"(smem_out) : "memory");
        asm volatile("cp.async.bulk.commit_group;" ::: "memory");
        asm volatile("cp.async.bulk.wait_group 0;" ::: "memory");
    }
}

// ---------------- fallback (round-4 kernel, proven 92.9us) -----------------
#define FB_THREADS 256
#define FB_CHUNKS 2
__global__ __launch_bounds__(FB_THREADS)
void li_fallback_kernel(const float* __restrict__ A,
                        const float* __restrict__ Kmat,
                        float* __restrict__ Out) {
    const int row = blockIdx.y;
    const int t   = threadIdx.x;
    const int p0  = blockIdx.x * (FB_THREADS * FB_CHUNKS) + t;
    const float4* __restrict__ arow4 =
        reinterpret_cast<const float4*>(A + (size_t)row * D_MODEL);
    float4* __restrict__ orow4 =
        reinterpret_cast<float4*>(Out + (size_t)row * D_MODEL);
    float w[NB + 1];
#pragma unroll
    for (int d = 1; d <= NB; d++) w[d] = __ldg(Kmat + d);
    float f[FB_CHUNKS][20];
#pragma unroll
    for (int c = 0; c < FB_CHUNKS; c++) {
        const int p = p0 + c * FB_THREADS;
        if (p >= 2 && p < ROW_F4 - 2) {
            const float4* __restrict__ base = arow4 + p;
#pragma unroll
            for (int m = 0; m < 5; m++) {
                float4 q = base[m - 2];
                f[c][4*m+0] = q.x; f[c][4*m+1] = q.y;
                f[c][4*m+2] = q.z; f[c][4*m+3] = q.w;
            }
        } else {
#pragma unroll
            for (int m = 0; m < 5; m++) {
                const int idx = p + m - 2;
                float4 q = make_float4(0.f, 0.f, 0.f, 0.f);
                if (idx >= 0 && idx < ROW_F4) q = arow4[idx];
                f[c][4*m+0] = q.x; f[c][4*m+1] = q.y;
                f[c][4*m+2] = q.z; f[c][4*m+3] = q.w;
            }
        }
    }
#pragma unroll
    for (int c = 0; c < FB_CHUNKS; c++) {
        float o[4];
#pragma unroll
        for (int k = 0; k < 4; k++) {
            const int ctr = NB + k;
            float acc = f[c][ctr];
#pragma unroll
            for (int d = 1; d <= NB; d++)
                acc = fmaf(w[d], f[c][ctr - d] + f[c][ctr + d], acc);
            o[k] = acc;
        }
        __stcs(orow4 + p0 + c * FB_THREADS, make_float4(o[0], o[1], o[2], o[3]));
    }
}

// ---------------- host: tensormap encode via driver entry point ------------
typedef CUresult (*PFN_encode)(
    CUtensorMap*, CUtensorMapDataType, cuuint32_t, void*,
    const cuuint64_t*, const cuuint64_t*, const cuuint32_t*, const cuuint32_t*,
    CUtensorMapInterleave, CUtensorMapSwizzle, CUtensorMapL2promotion,
    CUtensorMapFloatOOBfill);

static PFN_encode get_encode() {
    static PFN_encode fn = nullptr;
    static bool tried = false;
    if (!tried) {
        tried = true;
        void* p = nullptr;
        cudaDriverEntryPointQueryResult st;
#if CUDART_VERSION >= 12050
        if (cudaGetDriverEntryPointByVersion("cuTensorMapEncodeTiled", &p, 12000,
                                             cudaEnableDefault, &st) == cudaSuccess &&
            st == cudaDriverEntryPointSuccess && p)
            fn = (PFN_encode)p;
#else
        if (cudaGetDriverEntryPoint("cuTensorMapEncodeTiled", &p,
                                    cudaEnableDefault, &st) == cudaSuccess && p)
            fn = (PFN_encode)p;
#endif
    }
    return fn;
}

static bool make_map(PFN_encode enc, CUtensorMap* tm, void* base, int rows) {
    // View (rows, 4096) fp32 as 3D: dim0=32 floats (128B SW128 atom),
    // dim1=128 chunks, dim2=rows. Box = one full row.
    cuuint64_t dims[3]    = {32, 128, (cuuint64_t)rows};
    cuuint64_t strides[2] = {128, (cuuint64_t)D_MODEL * 4};  // bytes
    cuuint32_t box[3]     = {32, 128, 1};
    cuuint32_t es[3]      = {1, 1, 1};
    return enc(tm, CU_TENSOR_MAP_DATA_TYPE_FLOAT32, 3, base, dims, strides, box, es,
               CU_TENSOR_MAP_INTERLEAVE_NONE, CU_TENSOR_MAP_SWIZZLE_128B,
               CU_TENSOR_MAP_L2_PROMOTION_L2_128B,
               CU_TENSOR_MAP_FLOAT_OOB_FILL_NONE) == CUDA_SUCCESS;
}

extern "C" void kernel_launch(void* const* d_in, const int* in_sizes, int n_in,
                              void* d_out, int out_size) {
    const float* A    = (const float*)d_in[0];   // activations (rows, 4096)
    const float* Kmat = (const float*)d_in[1];   // inhibition kernel (4096, 4096)
    float* Out        = (float*)d_out;
    const int rows    = in_sizes[0] / D_MODEL;   // 16384

    PFN_encode enc = get_encode();
    if (enc) {
        CUtensorMap tmin, tmout;
        if (make_map(enc, &tmin, (void*)A, rows) &&
            make_map(enc, &tmout, (void*)Out, rows)) {
            li_tma_kernel<<<rows, TMA_THREADS>>>(tmin, tmout, Kmat);
            return;
        }
    }
    // Fallback: proven direct-LDG kernel
    dim3 grid(ROW_F4 / (FB_THREADS * FB_CHUNKS), rows);
    li_fallback_kernel<<<grid, FB_THREADS>>>(A, Kmat, Out);
}